// round 1
// baseline (speedup 1.0000x reference)
#include <cuda_runtime.h>
#include <cuda_bf16.h>

// Problem constants
#define BSZ 64
#define KREG 19
#define KALL 20          // 19 regions + 1 global (all-ones weight row)
#define CCH 384
#define PPIX 256         // 16x16
#define DOUT 256

// Scratch (device globals; no allocation allowed)
__device__ float g_wsmall[BSZ * KALL * PPIX];     // [b][k][p]
__device__ float g_allfeats[BSZ * KALL * CCH];    // [b][k][c]
__device__ float g_Wt[CCH * DOUT];                // [c][d]

// ---------------------------------------------------------------------------
// K0: transpose W [256 d][384 c] -> Wt [384 c][256 d]
// ---------------------------------------------------------------------------
__global__ void k0_transpose(const float* __restrict__ W) {
    __shared__ float ts[32][33];
    int c0 = blockIdx.x * 32;   // grid.x = 12
    int d0 = blockIdx.y * 32;   // grid.y = 8
    int tx = threadIdx.x, ty = threadIdx.y;  // 32 x 8
#pragma unroll
    for (int i = 0; i < 4; i++)
        ts[ty + 8 * i][tx] = W[(d0 + ty + 8 * i) * CCH + c0 + tx];
    __syncthreads();
#pragma unroll
    for (int i = 0; i < 4; i++)
        g_Wt[(c0 + ty + 8 * i) * DOUT + d0 + tx] = ts[tx][ty + 8 * i];
}

// ---------------------------------------------------------------------------
// K1: bilinear 256->16 downsample of seg_weights; row k=19 is all ones.
// Half-pixel centers: out(i,j) samples at (16i+7.5, 16j+7.5) ->
// 0.25*(s[16i+7][16j+7]+s[16i+7][16j+8]+s[16i+8][16j+7]+s[16i+8][16j+8])
// ---------------------------------------------------------------------------
__global__ void k1_downsample(const float* __restrict__ seg) {
    int bk = blockIdx.x;           // 0..1279  (b*20 + k)
    int b = bk / KALL;
    int k = bk % KALL;
    int p = threadIdx.x;           // 0..255
    float v;
    if (k < KREG) {
        int i = p >> 4, j = p & 15;
        const float* s = seg + (((size_t)(b * KREG + k) * 256 + (16 * i + 7)) * 256
                                + (16 * j + 7));
        v = 0.25f * (s[0] + s[1] + s[256] + s[257]);
    } else {
        v = 1.0f;                  // global mean row
    }
    g_wsmall[bk * PPIX + p] = v;
}

// ---------------------------------------------------------------------------
// K2: per-batch GEMM  A[b] = (1/256) * w[20 x 256] * F[b]^T[256 x 384]
// grid (64, 3): block handles (b, 128-channel tile). 256 threads.
// Thread tile: 5 k x 2 c (c pair {cg, cg+64}).  w-frag is warp-broadcast.
// F staged transposed in smem in 32-p chunks (stride 129: conflict-free reads,
// 4-way-max stores).
// ---------------------------------------------------------------------------
__global__ void k2_region_gemm(const float* __restrict__ F) {
    __shared__ float ws[PPIX * KALL];   // [p][k], stride 20
    __shared__ float fs[32 * 129];      // [p][c], stride 129

    int b = blockIdx.x;
    int c0 = blockIdx.y * 128;
    int t = threadIdx.x;                // 256

    // load w_small[b] (20*256 floats), transposed into [p][k]
    const float* wsm = g_wsmall + b * KALL * PPIX;
    for (int idx = t; idx < KALL * PPIX; idx += 256) {
        int k = idx >> 8, p = idx & 255;
        ws[p * KALL + k] = wsm[idx];
    }

    int cg = t & 63;        // c within tile: {cg, cg+64}
    int kg = t >> 6;        // k group: rows kg*5 .. kg*5+4
    float acc[5][2] = {};

    const float* Fb = F + ((size_t)b * CCH + c0) * PPIX;

    for (int pc = 0; pc < PPIX; pc += 32) {
        __syncthreads();
        // stage 128 c x 32 p (4096 floats = 1024 float4; 4 per thread)
#pragma unroll
        for (int r = 0; r < 4; r++) {
            int linear = r * 256 + t;          // float4 index
            int c = linear >> 3;               // 8 float4 per channel (32 p)
            int p4 = linear & 7;
            float4 v = *reinterpret_cast<const float4*>(Fb + c * PPIX + pc + p4 * 4);
            int p = p4 * 4;
            fs[(p + 0) * 129 + c] = v.x;
            fs[(p + 1) * 129 + c] = v.y;
            fs[(p + 2) * 129 + c] = v.z;
            fs[(p + 3) * 129 + c] = v.w;
        }
        __syncthreads();

#pragma unroll 4
        for (int p = 0; p < 32; p++) {
            const float* wr = ws + (pc + p) * KALL + kg * 5;
            float f0 = fs[p * 129 + cg];
            float f1 = fs[p * 129 + 64 + cg];
#pragma unroll
            for (int i = 0; i < 5; i++) {
                float w = wr[i];
                acc[i][0] = fmaf(w, f0, acc[i][0]);
                acc[i][1] = fmaf(w, f1, acc[i][1]);
            }
        }
    }

    const float inv = 1.0f / 256.0f;
    float* A = g_allfeats + ((size_t)b * KALL) * CCH + c0;
#pragma unroll
    for (int i = 0; i < 5; i++) {
        int k = kg * 5 + i;
        A[k * CCH + cg]      = acc[i][0] * inv;
        A[k * CCH + 64 + cg] = acc[i][1] * inv;
    }
}

// ---------------------------------------------------------------------------
// K3: projection  out[row][d] = relu(bias[d] + A[row][:] . Wt[:][d])
// rows = B*20 = 1280 = 256 blocks x 5 rows. 128 threads; thread = d pair
// {t, t+128}; A row staged in smem (broadcast reads), Wt read coalesced.
// ---------------------------------------------------------------------------
__global__ void k3_project(const float* __restrict__ bias, float* __restrict__ out) {
    __shared__ float As[5 * 385];
    int row0 = blockIdx.x * 5;     // grid 256
    int t = threadIdx.x;           // 128

    const float* Ar = g_allfeats + (size_t)row0 * CCH;
    for (int idx = t; idx < 5 * CCH; idx += 128) {
        int r = idx / CCH, c = idx - r * CCH;
        As[r * 385 + c] = Ar[idx];
    }
    __syncthreads();

    float b0 = bias[t];
    float b1 = bias[t + 128];
    float acc[5][2];
#pragma unroll
    for (int i = 0; i < 5; i++) { acc[i][0] = b0; acc[i][1] = b1; }

#pragma unroll 4
    for (int c = 0; c < CCH; c++) {
        float w0 = g_Wt[c * DOUT + t];
        float w1 = g_Wt[c * DOUT + 128 + t];
#pragma unroll
        for (int i = 0; i < 5; i++) {
            float a = As[i * 385 + c];
            acc[i][0] = fmaf(a, w0, acc[i][0]);
            acc[i][1] = fmaf(a, w1, acc[i][1]);
        }
    }

#pragma unroll
    for (int i = 0; i < 5; i++) {
        size_t o = (size_t)(row0 + i) * DOUT;
        out[o + t]       = fmaxf(acc[i][0], 0.0f);
        out[o + 128 + t] = fmaxf(acc[i][1], 0.0f);
    }
}

// ---------------------------------------------------------------------------
extern "C" void kernel_launch(void* const* d_in, const int* in_sizes, int n_in,
                              void* d_out, int out_size) {
    const float* F    = (const float*)d_in[0];   // [64,384,16,16]
    const float* seg  = (const float*)d_in[1];   // [64,19,256,256]
    const float* W    = (const float*)d_in[2];   // [256,384]
    const float* bias = (const float*)d_in[3];   // [256]
    float* out = (float*)d_out;                  // [64, 5120]

    k0_transpose<<<dim3(12, 8), dim3(32, 8)>>>(W);
    k1_downsample<<<BSZ * KALL, 256>>>(seg);
    k2_region_gemm<<<dim3(BSZ, 3), 256>>>(F);
    k3_project<<<256, 128>>>(bias, out);
}

// round 3
// speedup vs baseline: 1.5957x; 1.5957x over previous
#include <cuda_runtime.h>
#include <cuda_bf16.h>

// Problem constants
#define BSZ 64
#define KREG 19
#define KALL 20          // 19 regions + 1 global (all-ones weight row)
#define CCH 384
#define PPIX 256         // 16x16
#define DOUT 256

// Scratch (device globals; no allocation allowed)
__device__ float g_wsmall[BSZ * KALL * PPIX];     // [b][k][p]
__device__ float g_allfeats[BSZ * KALL * CCH];    // [b][k][c]
__device__ float g_Wt[CCH * DOUT];                // [c][d]

// ---- packed f32x2 helpers (Blackwell) --------------------------------------
__device__ __forceinline__ unsigned long long pack2(float lo, float hi) {
    unsigned long long r;
    asm("mov.b64 %0, {%1, %2};" : "=l"(r) : "f"(lo), "f"(hi));
    return r;
}
__device__ __forceinline__ void unpack2(unsigned long long v, float& lo, float& hi) {
    asm("mov.b64 {%0, %1}, %2;" : "=f"(lo), "=f"(hi) : "l"(v));
}
__device__ __forceinline__ unsigned long long ffma2(unsigned long long a,
                                                    unsigned long long b,
                                                    unsigned long long c) {
    unsigned long long d;
    asm("fma.rn.f32x2 %0, %1, %2, %3;" : "=l"(d) : "l"(a), "l"(b), "l"(c));
    return d;
}

// ---------------------------------------------------------------------------
// K0: transpose W [256 d][384 c] -> Wt [384 c][256 d]
// ---------------------------------------------------------------------------
__global__ void k0_transpose(const float* __restrict__ W) {
    __shared__ float ts[32][33];
    int c0 = blockIdx.x * 32;   // grid.x = 12
    int d0 = blockIdx.y * 32;   // grid.y = 8
    int tx = threadIdx.x, ty = threadIdx.y;  // 32 x 8
#pragma unroll
    for (int i = 0; i < 4; i++)
        ts[ty + 8 * i][tx] = W[(d0 + ty + 8 * i) * CCH + c0 + tx];
    __syncthreads();
#pragma unroll
    for (int i = 0; i < 4; i++)
        g_Wt[(c0 + ty + 8 * i) * DOUT + d0 + tx] = ts[tx][ty + 8 * i];
}

// ---------------------------------------------------------------------------
// K1: bilinear 256->16 downsample of seg_weights; row k=19 is all ones.
// out(i,j) = 0.25*(s[16i+7][16j+7]+s[16i+7][16j+8]+s[16i+8][16j+7]+s[16i+8][16j+8])
// ---------------------------------------------------------------------------
__global__ void k1_downsample(const float* __restrict__ seg) {
    int bk = blockIdx.x;           // 0..1279  (b*20 + k)
    int b = bk / KALL;
    int k = bk % KALL;
    int p = threadIdx.x;           // 0..255
    float v;
    if (k < KREG) {
        int i = p >> 4, j = p & 15;
        const float* s = seg + (((size_t)(b * KREG + k) * 256 + (16 * i + 7)) * 256
                                + (16 * j + 7));
        v = 0.25f * (s[0] + s[1] + s[256] + s[257]);
    } else {
        v = 1.0f;                  // global mean row
    }
    g_wsmall[bk * PPIX + p] = v;
}

// ---------------------------------------------------------------------------
// K2: per-batch GEMM  A[b] = (1/256) * w[20 x 256] * F[b]^T[256 x 384]
// ---------------------------------------------------------------------------
__global__ void k2_region_gemm(const float* __restrict__ F) {
    __shared__ float ws[PPIX * KALL];   // [p][k], stride 20
    __shared__ float fs[32 * 129];      // [p][c], stride 129

    int b = blockIdx.x;
    int c0 = blockIdx.y * 128;
    int t = threadIdx.x;                // 256

    const float* wsm = g_wsmall + b * KALL * PPIX;
    for (int idx = t; idx < KALL * PPIX; idx += 256) {
        int k = idx >> 8, p = idx & 255;
        ws[p * KALL + k] = wsm[idx];
    }

    int cg = t & 63;        // c within tile: {cg, cg+64}
    int kg = t >> 6;        // k group: rows kg*5 .. kg*5+4
    float acc[5][2] = {};

    const float* Fb = F + ((size_t)b * CCH + c0) * PPIX;

    for (int pc = 0; pc < PPIX; pc += 32) {
        __syncthreads();
#pragma unroll
        for (int r = 0; r < 4; r++) {
            int linear = r * 256 + t;          // float4 index
            int c = linear >> 3;               // 8 float4 per channel (32 p)
            int p4 = linear & 7;
            float4 v = *reinterpret_cast<const float4*>(Fb + c * PPIX + pc + p4 * 4);
            int p = p4 * 4;
            fs[(p + 0) * 129 + c] = v.x;
            fs[(p + 1) * 129 + c] = v.y;
            fs[(p + 2) * 129 + c] = v.z;
            fs[(p + 3) * 129 + c] = v.w;
        }
        __syncthreads();

#pragma unroll 4
        for (int p = 0; p < 32; p++) {
            const float* wr = ws + (pc + p) * KALL + kg * 5;
            float f0 = fs[p * 129 + cg];
            float f1 = fs[p * 129 + 64 + cg];
#pragma unroll
            for (int i = 0; i < 5; i++) {
                float w = wr[i];
                acc[i][0] = fmaf(w, f0, acc[i][0]);
                acc[i][1] = fmaf(w, f1, acc[i][1]);
            }
        }
    }

    const float inv = 1.0f / 256.0f;
    float* A = g_allfeats + ((size_t)b * KALL) * CCH + c0;
#pragma unroll
    for (int i = 0; i < 5; i++) {
        int k = kg * 5 + i;
        A[k * CCH + cg]      = acc[i][0] * inv;
        A[k * CCH + 64 + cg] = acc[i][1] * inv;
    }
}

// ---------------------------------------------------------------------------
// K3: projection  out[row][d] = relu(bias[d] + A[row][:] . Wt[:][d])
// New design: grid = 128 blocks (10 rows each), 256 threads (thread = d).
//  - A tile (10 x 384) staged TRANSPOSED in smem -> warp-broadcast reads.
//  - Wt streamed through double-buffered smem chunks (16 k-rows each),
//    register-prefetched LDG -> STS, one __syncthreads per chunk.
//  - Row-pair accumulators via packed fma.rn.f32x2 (2 FMA lanes / instr).
// ---------------------------------------------------------------------------
#define K3_ROWS   10
#define K3_CHUNK  16
#define K3_NCHNK  (CCH / K3_CHUNK)   // 24

__global__ __launch_bounds__(256, 1)
void k3_project(const float* __restrict__ bias, float* __restrict__ out) {
    __shared__ float as2f[CCH * K3_ROWS];          // [k][r]   15360 B
    __shared__ float wsm[2][K3_CHUNK * DOUT];      // [buf][kk][d]  2x16384 B

    int t = threadIdx.x;                 // 0..255 == this thread's d
    int row0 = blockIdx.x * K3_ROWS;

    // stage A rows transposed: as2f[k*10 + r] = A[row0+r][k]
    const float* Ar = g_allfeats + (size_t)row0 * CCH;
    for (int idx = t; idx < K3_ROWS * CCH; idx += 256) {
        int r = idx / CCH;
        int k = idx - r * CCH;
        as2f[k * K3_ROWS + r] = Ar[idx];
    }

    // prefetch chunk 0 of Wt (16 rows x 256 d = 1024 float4, 4 per thread)
    const float4* WtV = reinterpret_cast<const float4*>(g_Wt);
    float4 pf[4];
#pragma unroll
    for (int i = 0; i < 4; i++) pf[i] = WtV[i * 256 + t];

    float bv = bias[t];
    unsigned long long acc[5];
#pragma unroll
    for (int i = 0; i < 5; i++) acc[i] = pack2(bv, bv);

    for (int c = 0; c < K3_NCHNK; c++) {
        // commit prefetched chunk into smem buffer c&1
        float4* wb = reinterpret_cast<float4*>(wsm[c & 1]);
#pragma unroll
        for (int i = 0; i < 4; i++) wb[i * 256 + t] = pf[i];
        __syncthreads();

        // issue next chunk's global loads early (overlap with compute)
        if (c < K3_NCHNK - 1) {
#pragma unroll
            for (int i = 0; i < 4; i++)
                pf[i] = WtV[(c + 1) * 1024 + i * 256 + t];
        }

        const float* wrow = wsm[c & 1];
#pragma unroll
        for (int kk = 0; kk < K3_CHUNK; kk++) {
            int k = c * K3_CHUNK + kk;
            const float2* a2 = reinterpret_cast<const float2*>(as2f + k * K3_ROWS);
            float w = wrow[kk * DOUT + t];
            unsigned long long wv = pack2(w, w);
#pragma unroll
            for (int i = 0; i < 5; i++) {
                float2 av = a2[i];                    // rows {2i, 2i+1}, broadcast
                acc[i] = ffma2(pack2(av.x, av.y), wv, acc[i]);
            }
        }
        // no trailing sync needed: next iteration writes the OTHER buffer,
        // whose readers all passed this iteration's __syncthreads already.
        __syncthreads();
    }

#pragma unroll
    for (int i = 0; i < 5; i++) {
        float lo, hi;
        unpack2(acc[i], lo, hi);
        out[(size_t)(row0 + 2 * i) * DOUT + t]     = fmaxf(lo, 0.0f);
        out[(size_t)(row0 + 2 * i + 1) * DOUT + t] = fmaxf(hi, 0.0f);
    }
}

// ---------------------------------------------------------------------------
extern "C" void kernel_launch(void* const* d_in, const int* in_sizes, int n_in,
                              void* d_out, int out_size) {
    const float* F    = (const float*)d_in[0];   // [64,384,16,16]
    const float* seg  = (const float*)d_in[1];   // [64,19,256,256]
    const float* W    = (const float*)d_in[2];   // [256,384]
    const float* bias = (const float*)d_in[3];   // [256]
    float* out = (float*)d_out;                  // [64, 5120]

    k0_transpose<<<dim3(12, 8), dim3(32, 8)>>>(W);
    k1_downsample<<<BSZ * KALL, 256>>>(seg);
    k2_region_gemm<<<dim3(BSZ, 3), 256>>>(F);
    k3_project<<<128, 256>>>(bias, out);
}